// round 5
// baseline (speedup 1.0000x reference)
#include <cuda_runtime.h>
#include <cuda_bf16.h>
#include <math.h>
#include <stdint.h>

// ---------------------------------------------------------------------------
// Problem constants (fixed by setup_inputs)
// ---------------------------------------------------------------------------
#define HDIM 2048
#define NEXP 16
#define TOPK 4
#define IDIM 1408
#define ISDIM 5632
#define TMAX 8192

// ---------------------------------------------------------------------------
// Device scratch (no allocations allowed anywhere)
//   T*Is == T*K*I == 46,137,344 floats (184.5 MB each) -> reuse between
//   shared-expert phase and routed phase (kernels are stream-ordered).
// ---------------------------------------------------------------------------
#define SCRATCH_ELEMS 46137344
__device__ float g_scratchG[SCRATCH_ELEMS];
__device__ float g_scratchH[SCRATCH_ELEMS];
__device__ int   g_topi[TMAX * TOPK];
__device__ float g_topw[TMAX * TOPK];
__device__ float g_gate[TMAX];
__device__ int   g_counts[NEXP];
__device__ int   g_offsets[NEXP];
__device__ int   g_cursor[NEXP];
__device__ int   g_btok[TMAX * TOPK];
__device__ float g_bw[TMAX * TOPK];

// ---------------------------------------------------------------------------
// f32x2 packed-FMA helpers (Blackwell FFMA2 path, 2 FMA/lane/instr)
// ---------------------------------------------------------------------------
__device__ __forceinline__ unsigned long long pk2(float lo, float hi) {
    unsigned long long r;
    asm("mov.b64 %0, {%1, %2};" : "=l"(r) : "f"(lo), "f"(hi));
    return r;
}
__device__ __forceinline__ unsigned long long fma2(unsigned long long a,
                                                   unsigned long long b,
                                                   unsigned long long c) {
    unsigned long long d;
    asm("fma.rn.f32x2 %0, %1, %2, %3;" : "=l"(d) : "l"(a), "l"(b), "l"(c));
    return d;
}
__device__ __forceinline__ float2 upk2(unsigned long long v) {
    float2 r;
    asm("mov.b64 {%0, %1}, %2;" : "=f"(r.x), "=f"(r.y) : "l"(v));
    return r;
}

// ---------------------------------------------------------------------------
// Router: logits = x @ gate_w  (16), sg = x @ sg_w (1)
//   softmax -> top-4 (no renorm), sigmoid gate; per-expert counts via atomics
//   One block (256 threads) per token.
// ---------------------------------------------------------------------------
__global__ void router_k(const float* __restrict__ x,
                         const float* __restrict__ gw,
                         const float* __restrict__ sgw,
                         int* __restrict__ topi, float* __restrict__ topw,
                         float* __restrict__ gatev, int* __restrict__ counts) {
    int t = blockIdx.x;
    const float* xr = x + (size_t)t * HDIM;

    float acc[17];
#pragma unroll
    for (int e = 0; e < 17; e++) acc[e] = 0.f;

    for (int h = threadIdx.x; h < HDIM; h += blockDim.x) {
        float xv = xr[h];
        const float* g = gw + h * NEXP;
#pragma unroll
        for (int e = 0; e < NEXP; e++) acc[e] += xv * g[e];
        acc[16] += xv * sgw[h];
    }

    __shared__ float red[17][8];
    int lane = threadIdx.x & 31, w = threadIdx.x >> 5;
#pragma unroll
    for (int e = 0; e < 17; e++) {
        float v = acc[e];
#pragma unroll
        for (int o = 16; o; o >>= 1) v += __shfl_down_sync(0xffffffffu, v, o);
        if (lane == 0) red[e][w] = v;
    }
    __syncthreads();

    if (threadIdx.x == 0) {
        float l[17];
#pragma unroll
        for (int e = 0; e < 17; e++) {
            float s = 0.f;
#pragma unroll
            for (int i = 0; i < 8; i++) s += red[e][i];
            l[e] = s;
        }
        // softmax over experts
        float mx = l[0];
#pragma unroll
        for (int e = 1; e < NEXP; e++) mx = fmaxf(mx, l[e]);
        float p[NEXP], sum = 0.f;
#pragma unroll
        for (int e = 0; e < NEXP; e++) { p[e] = expf(l[e] - mx); sum += p[e]; }
        float inv = 1.f / sum;
        // top-4 (strict >, keeps lowest index on ties like jax top_k)
        bool used[NEXP];
#pragma unroll
        for (int e = 0; e < NEXP; e++) used[e] = false;
        for (int k = 0; k < TOPK; k++) {
            int best = 0; float bv = -1.f;
#pragma unroll
            for (int e = 0; e < NEXP; e++)
                if (!used[e] && p[e] > bv) { bv = p[e]; best = e; }
            used[best] = true;
            topi[t * TOPK + k] = best;
            topw[t * TOPK + k] = bv * inv;
            atomicAdd(&counts[best], 1);
        }
        gatev[t] = 1.f / (1.f + expf(-l[16]));
    }
}

__global__ void zero_counts_k(int* __restrict__ counts) {
    if (threadIdx.x < NEXP) counts[threadIdx.x] = 0;
}

__global__ void prefix_k(const int* __restrict__ counts,
                         int* __restrict__ offsets, int* __restrict__ cursor) {
    if (threadIdx.x == 0) {
        int s = 0;
        for (int e = 0; e < NEXP; e++) {
            offsets[e] = s; cursor[e] = s; s += counts[e];
        }
    }
}

__global__ void scatter_k(const int* __restrict__ topi,
                          const float* __restrict__ topw,
                          int* __restrict__ cursor,
                          int* __restrict__ btok, float* __restrict__ bw,
                          int TK) {
    int i = blockIdx.x * blockDim.x + threadIdx.x;
    if (i < TK) {
        int e = topi[i];
        int pos = atomicAdd(&cursor[e], 1);
        btok[pos] = i >> 2;   // token id
        bw[pos] = topw[i];
    }
}

// ---------------------------------------------------------------------------
// Tiled SGEMM, 128x128 tile, BK=16, 256 threads, 8x8 per thread, f32x2 FMAs.
//   MODE 0 (STORE):      C[(off+m)*N+n] = acc
//   MODE 1 (SILUMUL):    C[idx] = silu(G[idx]) * acc
//   MODE 2 (SCALESTORE): C[m*N+n] = rowscale[m] * acc       (dense out write)
//   MODE 3 (SCATTER):    atomicAdd(&C[tok*N+n], w * acc)    (routed combine)
// ROUTED: blockIdx.z = expert; rows bounded by counts[e]; B += e*Kd*N;
//         A-rows gathered through btok (MODE 0/1) or compact (MODE 3).
// ---------------------------------------------------------------------------
#define M_STORE 0
#define M_SILUMUL 1
#define M_SCALESTORE 2
#define M_SCATTER 3

#define BM 128
#define BN 128
#define BKT 16

template <int MODE, bool ROUTED>
__global__ void __launch_bounds__(256, 2)
gemm_k(const float* __restrict__ A, const float* __restrict__ Bmat,
       float* __restrict__ C, const float* __restrict__ Gbuf,
       const float* __restrict__ rowscale,
       const int* __restrict__ counts, const int* __restrict__ offsets,
       const int* __restrict__ btok, const float* __restrict__ bw,
       int M, int N, int Kd) {
    __shared__ float As[BKT][BM + 4];
    __shared__ float Bs[BKT][BN];

    int off = 0;
    int Ne = M;
    const float* B = Bmat;
    if (ROUTED) {
        int e = blockIdx.z;
        Ne = counts[e];
        off = offsets[e];
        B = Bmat + (size_t)e * Kd * N;
    }
    int rowblock = blockIdx.y * BM;
    if (rowblock >= Ne) return;        // uniform per block -> safe early exit
    int colblock = blockIdx.x * BN;

    int tid = threadIdx.x;

    // A-tile loader: thread loads float4 at (row = ar0 + 64*i, k = ak)
    int ak = (tid & 3) * 4;
    int ar0 = tid >> 2;
    const float* aptr[2];
#pragma unroll
    for (int i = 0; i < 2; i++) {
        int r = ar0 + 64 * i;
        int m = rowblock + r;
        const float* p = nullptr;
        if (m < Ne) {
            if (ROUTED) {
                if (MODE == M_SCATTER) {
                    p = A + (size_t)(off + m) * Kd;        // compact rows
                } else {
                    int tok = btok[off + m];               // gathered rows
                    p = A + (size_t)tok * Kd;
                }
            } else {
                p = A + (size_t)m * Kd;
            }
        }
        aptr[i] = p;
    }
    // B-tile loader: thread loads float4 at (row = br0 + 8*i, col = bc)
    int br0 = tid >> 5;
    int bc = (tid & 31) * 4;

    // Per-thread output: rows tm..tm+7, cols {colA..+3, colA+64..+67}
    int tm = (tid >> 4) * 8;
    int colA = (tid & 15) * 4;

    unsigned long long acc[8][4];
#pragma unroll
    for (int i = 0; i < 8; i++)
#pragma unroll
        for (int j = 0; j < 4; j++) acc[i][j] = 0ull;

    for (int k0 = 0; k0 < Kd; k0 += BKT) {
#pragma unroll
        for (int i = 0; i < 2; i++) {
            float4 v = make_float4(0.f, 0.f, 0.f, 0.f);
            if (aptr[i]) v = *reinterpret_cast<const float4*>(aptr[i] + k0 + ak);
            int r = ar0 + 64 * i;
            As[ak + 0][r] = v.x;
            As[ak + 1][r] = v.y;
            As[ak + 2][r] = v.z;
            As[ak + 3][r] = v.w;
        }
#pragma unroll
        for (int i = 0; i < 2; i++) {
            int r = br0 + 8 * i;
            float4 v = *reinterpret_cast<const float4*>(
                B + (size_t)(k0 + r) * N + colblock + bc);
            *reinterpret_cast<float4*>(&Bs[r][bc]) = v;
        }
        __syncthreads();

#pragma unroll
        for (int kk = 0; kk < BKT; kk++) {
            float4 a0 = *reinterpret_cast<const float4*>(&As[kk][tm]);
            float4 a1 = *reinterpret_cast<const float4*>(&As[kk][tm + 4]);
            float4 bA = *reinterpret_cast<const float4*>(&Bs[kk][colA]);
            float4 bB = *reinterpret_cast<const float4*>(&Bs[kk][colA + 64]);
            unsigned long long b2[4];
            b2[0] = pk2(bA.x, bA.y);
            b2[1] = pk2(bA.z, bA.w);
            b2[2] = pk2(bB.x, bB.y);
            b2[3] = pk2(bB.z, bB.w);
            float a[8] = {a0.x, a0.y, a0.z, a0.w, a1.x, a1.y, a1.z, a1.w};
#pragma unroll
            for (int i = 0; i < 8; i++) {
                unsigned long long a2 = pk2(a[i], a[i]);
#pragma unroll
                for (int j = 0; j < 4; j++) acc[i][j] = fma2(a2, b2[j], acc[i][j]);
            }
        }
        __syncthreads();
    }

    // Epilogue
#pragma unroll
    for (int i = 0; i < 8; i++) {
        int m = rowblock + tm + i;
        if (m >= Ne) break;
        float scale = 1.f;
        int tok = 0;
        if (MODE == M_SCATTER) {
            tok = btok[off + m];
            scale = bw[off + m];
        } else if (MODE == M_SCALESTORE) {
            scale = rowscale[m];
        }
#pragma unroll
        for (int j = 0; j < 4; j++) {
            float2 v = upk2(acc[i][j]);
            int n = colblock + ((j < 2) ? (colA + 2 * j) : (colA + 64 + 2 * (j - 2)));
            if (MODE == M_STORE) {
                size_t idx = (size_t)(off + m) * N + n;
                *reinterpret_cast<float2*>(&C[idx]) = v;
            } else if (MODE == M_SILUMUL) {
                size_t idx = (size_t)(off + m) * N + n;
                float2 g = *reinterpret_cast<const float2*>(&Gbuf[idx]);
                float2 o;
                o.x = (g.x / (1.f + expf(-g.x))) * v.x;
                o.y = (g.y / (1.f + expf(-g.y))) * v.y;
                *reinterpret_cast<float2*>(&C[idx]) = o;
            } else if (MODE == M_SCALESTORE) {
                size_t idx = (size_t)m * N + n;
                float2 o = make_float2(scale * v.x, scale * v.y);
                *reinterpret_cast<float2*>(&C[idx]) = o;
            } else {  // M_SCATTER
                size_t idx = (size_t)tok * N + n;
                atomicAdd(&C[idx], scale * v.x);
                atomicAdd(&C[idx + 1], scale * v.y);
            }
        }
    }
}

// ---------------------------------------------------------------------------
// kernel_launch
// ---------------------------------------------------------------------------
extern "C" void kernel_launch(void* const* d_in, const int* in_sizes, int n_in,
                              void* d_out, int out_size) {
    const float* x   = (const float*)d_in[0];  // [T, H]
    const float* gw  = (const float*)d_in[1];  // [H, E]
    const float* w1  = (const float*)d_in[2];  // [E, H, I]
    const float* w3  = (const float*)d_in[3];  // [E, H, I]
    const float* w2  = (const float*)d_in[4];  // [E, I, H]
    const float* sw1 = (const float*)d_in[5];  // [H, Is]
    const float* sw3 = (const float*)d_in[6];  // [H, Is]
    const float* sw2 = (const float*)d_in[7];  // [Is, H]
    const float* sgw = (const float*)d_in[8];  // [H, 1]
    float* out = (float*)d_out;

    const int T = in_sizes[0] / HDIM;  // 8192
    const int TK = T * TOPK;

    // resolve device-global scratch addresses (host API, not a stream op)
    float *sG, *sH, *topw, *bw, *gatev;
    int *topi, *counts, *offsets, *cursor, *btok;
    cudaGetSymbolAddress((void**)&sG, g_scratchG);
    cudaGetSymbolAddress((void**)&sH, g_scratchH);
    cudaGetSymbolAddress((void**)&topi, g_topi);
    cudaGetSymbolAddress((void**)&topw, g_topw);
    cudaGetSymbolAddress((void**)&gatev, g_gate);
    cudaGetSymbolAddress((void**)&counts, g_counts);
    cudaGetSymbolAddress((void**)&offsets, g_offsets);
    cudaGetSymbolAddress((void**)&cursor, g_cursor);
    cudaGetSymbolAddress((void**)&btok, g_btok);
    cudaGetSymbolAddress((void**)&bw, g_bw);

    // ---- routing ----
    zero_counts_k<<<1, 32>>>(counts);
    router_k<<<T, 256>>>(x, gw, sgw, topi, topw, gatev, counts);
    prefix_k<<<1, 32>>>(counts, offsets, cursor);
    scatter_k<<<(TK + 255) / 256, 256>>>(topi, topw, cursor, btok, bw, TK);

    // ---- shared expert: out = sigmoid(x@sg_w) * ((silu(x@sw1) * (x@sw3)) @ sw2)
    {
        dim3 grid1(ISDIM / BN, T / BM);
        gemm_k<M_STORE, false><<<grid1, 256>>>(
            x, sw1, sG, nullptr, nullptr, nullptr, nullptr, nullptr, nullptr,
            T, ISDIM, HDIM);
        gemm_k<M_SILUMUL, false><<<grid1, 256>>>(
            x, sw3, sH, sG, nullptr, nullptr, nullptr, nullptr, nullptr,
            T, ISDIM, HDIM);
        dim3 grid2(HDIM / BN, T / BM);
        gemm_k<M_SCALESTORE, false><<<grid2, 256>>>(
            sH, sw2, out, nullptr, gatev, nullptr, nullptr, nullptr, nullptr,
            T, HDIM, ISDIM);   // writes ALL of d_out (covers 0xAA poison)
    }

    // ---- routed experts (token-grouped, sparse) ----
    {
        dim3 grid1(IDIM / BN, T / BM, NEXP);
        gemm_k<M_STORE, true><<<grid1, 256>>>(
            x, w1, sG, nullptr, nullptr, counts, offsets, btok, bw,
            T, IDIM, HDIM);
        gemm_k<M_SILUMUL, true><<<grid1, 256>>>(
            x, w3, sH, sG, nullptr, counts, offsets, btok, bw,
            T, IDIM, HDIM);
        dim3 grid2(HDIM / BN, T / BM, NEXP);
        gemm_k<M_SCATTER, true><<<grid2, 256>>>(
            sH, w2, out, nullptr, nullptr, counts, offsets, btok, bw,
            T, HDIM, IDIM);
    }
}

// round 6
// speedup vs baseline: 1.0007x; 1.0007x over previous
#include <cuda_runtime.h>
#include <cuda_bf16.h>
#include <math.h>
#include <stdint.h>

// ---------------------------------------------------------------------------
// Problem constants (fixed by setup_inputs)
// ---------------------------------------------------------------------------
#define HDIM 2048
#define NEXP 16
#define TOPK 4
#define IDIM 1408
#define ISDIM 5632
#define TMAX 8192

// ---------------------------------------------------------------------------
// Device scratch (no allocations allowed anywhere)
//   T*Is == T*K*I == 46,137,344 floats (184.5 MB each) -> reuse between
//   shared-expert phase and routed phase (kernels are stream-ordered).
// ---------------------------------------------------------------------------
#define SCRATCH_ELEMS 46137344
__device__ float g_scratchG[SCRATCH_ELEMS];
__device__ float g_scratchH[SCRATCH_ELEMS];
__device__ int   g_topi[TMAX * TOPK];
__device__ float g_topw[TMAX * TOPK];
__device__ float g_gate[TMAX];
__device__ int   g_counts[NEXP];
__device__ int   g_offsets[NEXP];
__device__ int   g_cursor[NEXP];
__device__ int   g_btok[TMAX * TOPK];
__device__ float g_bw[TMAX * TOPK];

// ---------------------------------------------------------------------------
// f32x2 packed-FMA helpers (Blackwell FFMA2 path, 2 FMA/lane/instr)
// ---------------------------------------------------------------------------
__device__ __forceinline__ unsigned long long pk2(float lo, float hi) {
    unsigned long long r;
    asm("mov.b64 %0, {%1, %2};" : "=l"(r) : "f"(lo), "f"(hi));
    return r;
}
__device__ __forceinline__ unsigned long long fma2(unsigned long long a,
                                                   unsigned long long b,
                                                   unsigned long long c) {
    unsigned long long d;
    asm("fma.rn.f32x2 %0, %1, %2, %3;" : "=l"(d) : "l"(a), "l"(b), "l"(c));
    return d;
}
__device__ __forceinline__ float2 upk2(unsigned long long v) {
    float2 r;
    asm("mov.b64 {%0, %1}, %2;" : "=f"(r.x), "=f"(r.y) : "l"(v));
    return r;
}

// ---------------------------------------------------------------------------
// Router: logits = x @ gate_w  (16), sg = x @ sg_w (1)
//   softmax -> top-4 (no renorm), sigmoid gate; per-expert counts via atomics
//   One block (256 threads) per token.
// ---------------------------------------------------------------------------
__global__ void router_k(const float* __restrict__ x,
                         const float* __restrict__ gw,
                         const float* __restrict__ sgw,
                         int* __restrict__ topi, float* __restrict__ topw,
                         float* __restrict__ gatev, int* __restrict__ counts) {
    int t = blockIdx.x;
    const float* xr = x + (size_t)t * HDIM;

    float acc[17];
#pragma unroll
    for (int e = 0; e < 17; e++) acc[e] = 0.f;

    for (int h = threadIdx.x; h < HDIM; h += blockDim.x) {
        float xv = xr[h];
        const float* g = gw + h * NEXP;
#pragma unroll
        for (int e = 0; e < NEXP; e++) acc[e] += xv * g[e];
        acc[16] += xv * sgw[h];
    }

    __shared__ float red[17][8];
    int lane = threadIdx.x & 31, w = threadIdx.x >> 5;
#pragma unroll
    for (int e = 0; e < 17; e++) {
        float v = acc[e];
#pragma unroll
        for (int o = 16; o; o >>= 1) v += __shfl_down_sync(0xffffffffu, v, o);
        if (lane == 0) red[e][w] = v;
    }
    __syncthreads();

    if (threadIdx.x == 0) {
        float l[17];
#pragma unroll
        for (int e = 0; e < 17; e++) {
            float s = 0.f;
#pragma unroll
            for (int i = 0; i < 8; i++) s += red[e][i];
            l[e] = s;
        }
        // softmax over experts
        float mx = l[0];
#pragma unroll
        for (int e = 1; e < NEXP; e++) mx = fmaxf(mx, l[e]);
        float p[NEXP], sum = 0.f;
#pragma unroll
        for (int e = 0; e < NEXP; e++) { p[e] = expf(l[e] - mx); sum += p[e]; }
        float inv = 1.f / sum;
        // top-4 (strict >, keeps lowest index on ties like jax top_k)
        bool used[NEXP];
#pragma unroll
        for (int e = 0; e < NEXP; e++) used[e] = false;
        for (int k = 0; k < TOPK; k++) {
            int best = 0; float bv = -1.f;
#pragma unroll
            for (int e = 0; e < NEXP; e++)
                if (!used[e] && p[e] > bv) { bv = p[e]; best = e; }
            used[best] = true;
            topi[t * TOPK + k] = best;
            topw[t * TOPK + k] = bv * inv;
            atomicAdd(&counts[best], 1);
        }
        gatev[t] = 1.f / (1.f + expf(-l[16]));
    }
}

__global__ void zero_counts_k(int* __restrict__ counts) {
    if (threadIdx.x < NEXP) counts[threadIdx.x] = 0;
}

__global__ void prefix_k(const int* __restrict__ counts,
                         int* __restrict__ offsets, int* __restrict__ cursor) {
    if (threadIdx.x == 0) {
        int s = 0;
        for (int e = 0; e < NEXP; e++) {
            offsets[e] = s; cursor[e] = s; s += counts[e];
        }
    }
}

__global__ void scatter_k(const int* __restrict__ topi,
                          const float* __restrict__ topw,
                          int* __restrict__ cursor,
                          int* __restrict__ btok, float* __restrict__ bw,
                          int TK) {
    int i = blockIdx.x * blockDim.x + threadIdx.x;
    if (i < TK) {
        int e = topi[i];
        int pos = atomicAdd(&cursor[e], 1);
        btok[pos] = i >> 2;   // token id
        bw[pos] = topw[i];
    }
}

// ---------------------------------------------------------------------------
// Tiled SGEMM, 128x128 tile, BK=16, 256 threads, 8x8 per thread, f32x2 FMAs.
//   MODE 0 (STORE):      C[(off+m)*N+n] = acc
//   MODE 1 (SILUMUL):    C[idx] = silu(G[idx]) * acc
//   MODE 2 (SCALESTORE): C[m*N+n] = rowscale[m] * acc       (dense out write)
//   MODE 3 (SCATTER):    atomicAdd(&C[tok*N+n], w * acc)    (routed combine)
// ROUTED: blockIdx.z = expert; rows bounded by counts[e]; B += e*Kd*N;
//         A-rows gathered through btok (MODE 0/1) or compact (MODE 3).
// ---------------------------------------------------------------------------
#define M_STORE 0
#define M_SILUMUL 1
#define M_SCALESTORE 2
#define M_SCATTER 3

#define BM 128
#define BN 128
#define BKT 16

template <int MODE, bool ROUTED>
__global__ void __launch_bounds__(256, 2)
gemm_k(const float* __restrict__ A, const float* __restrict__ Bmat,
       float* __restrict__ C, const float* __restrict__ Gbuf,
       const float* __restrict__ rowscale,
       const int* __restrict__ counts, const int* __restrict__ offsets,
       const int* __restrict__ btok, const float* __restrict__ bw,
       int M, int N, int Kd) {
    __shared__ float As[BKT][BM + 4];
    __shared__ float Bs[BKT][BN];

    int off = 0;
    int Ne = M;
    const float* B = Bmat;
    if (ROUTED) {
        int e = blockIdx.z;
        Ne = counts[e];
        off = offsets[e];
        B = Bmat + (size_t)e * Kd * N;
    }
    int rowblock = blockIdx.y * BM;
    if (rowblock >= Ne) return;        // uniform per block -> safe early exit
    int colblock = blockIdx.x * BN;

    int tid = threadIdx.x;

    // A-tile loader: thread loads float4 at (row = ar0 + 64*i, k = ak)
    int ak = (tid & 3) * 4;
    int ar0 = tid >> 2;
    const float* aptr[2];
#pragma unroll
    for (int i = 0; i < 2; i++) {
        int r = ar0 + 64 * i;
        int m = rowblock + r;
        const float* p = nullptr;
        if (m < Ne) {
            if (ROUTED) {
                if (MODE == M_SCATTER) {
                    p = A + (size_t)(off + m) * Kd;        // compact rows
                } else {
                    int tok = btok[off + m];               // gathered rows
                    p = A + (size_t)tok * Kd;
                }
            } else {
                p = A + (size_t)m * Kd;
            }
        }
        aptr[i] = p;
    }
    // B-tile loader: thread loads float4 at (row = br0 + 8*i, col = bc)
    int br0 = tid >> 5;
    int bc = (tid & 31) * 4;

    // Per-thread output: rows tm..tm+7, cols {colA..+3, colA+64..+67}
    int tm = (tid >> 4) * 8;
    int colA = (tid & 15) * 4;

    unsigned long long acc[8][4];
#pragma unroll
    for (int i = 0; i < 8; i++)
#pragma unroll
        for (int j = 0; j < 4; j++) acc[i][j] = 0ull;

    for (int k0 = 0; k0 < Kd; k0 += BKT) {
#pragma unroll
        for (int i = 0; i < 2; i++) {
            float4 v = make_float4(0.f, 0.f, 0.f, 0.f);
            if (aptr[i]) v = *reinterpret_cast<const float4*>(aptr[i] + k0 + ak);
            int r = ar0 + 64 * i;
            As[ak + 0][r] = v.x;
            As[ak + 1][r] = v.y;
            As[ak + 2][r] = v.z;
            As[ak + 3][r] = v.w;
        }
#pragma unroll
        for (int i = 0; i < 2; i++) {
            int r = br0 + 8 * i;
            float4 v = *reinterpret_cast<const float4*>(
                B + (size_t)(k0 + r) * N + colblock + bc);
            *reinterpret_cast<float4*>(&Bs[r][bc]) = v;
        }
        __syncthreads();

#pragma unroll
        for (int kk = 0; kk < BKT; kk++) {
            float4 a0 = *reinterpret_cast<const float4*>(&As[kk][tm]);
            float4 a1 = *reinterpret_cast<const float4*>(&As[kk][tm + 4]);
            float4 bA = *reinterpret_cast<const float4*>(&Bs[kk][colA]);
            float4 bB = *reinterpret_cast<const float4*>(&Bs[kk][colA + 64]);
            unsigned long long b2[4];
            b2[0] = pk2(bA.x, bA.y);
            b2[1] = pk2(bA.z, bA.w);
            b2[2] = pk2(bB.x, bB.y);
            b2[3] = pk2(bB.z, bB.w);
            float a[8] = {a0.x, a0.y, a0.z, a0.w, a1.x, a1.y, a1.z, a1.w};
#pragma unroll
            for (int i = 0; i < 8; i++) {
                unsigned long long a2 = pk2(a[i], a[i]);
#pragma unroll
                for (int j = 0; j < 4; j++) acc[i][j] = fma2(a2, b2[j], acc[i][j]);
            }
        }
        __syncthreads();
    }

    // Epilogue
#pragma unroll
    for (int i = 0; i < 8; i++) {
        int m = rowblock + tm + i;
        if (m >= Ne) break;
        float scale = 1.f;
        int tok = 0;
        if (MODE == M_SCATTER) {
            tok = btok[off + m];
            scale = bw[off + m];
        } else if (MODE == M_SCALESTORE) {
            scale = rowscale[m];
        }
#pragma unroll
        for (int j = 0; j < 4; j++) {
            float2 v = upk2(acc[i][j]);
            int n = colblock + ((j < 2) ? (colA + 2 * j) : (colA + 64 + 2 * (j - 2)));
            if (MODE == M_STORE) {
                size_t idx = (size_t)(off + m) * N + n;
                *reinterpret_cast<float2*>(&C[idx]) = v;
            } else if (MODE == M_SILUMUL) {
                size_t idx = (size_t)(off + m) * N + n;
                float2 g = *reinterpret_cast<const float2*>(&Gbuf[idx]);
                float2 o;
                o.x = (g.x / (1.f + expf(-g.x))) * v.x;
                o.y = (g.y / (1.f + expf(-g.y))) * v.y;
                *reinterpret_cast<float2*>(&C[idx]) = o;
            } else if (MODE == M_SCALESTORE) {
                size_t idx = (size_t)m * N + n;
                float2 o = make_float2(scale * v.x, scale * v.y);
                *reinterpret_cast<float2*>(&C[idx]) = o;
            } else {  // M_SCATTER
                size_t idx = (size_t)tok * N + n;
                atomicAdd(&C[idx], scale * v.x);
                atomicAdd(&C[idx + 1], scale * v.y);
            }
        }
    }
}

// ---------------------------------------------------------------------------
// kernel_launch
// ---------------------------------------------------------------------------
extern "C" void kernel_launch(void* const* d_in, const int* in_sizes, int n_in,
                              void* d_out, int out_size) {
    const float* x   = (const float*)d_in[0];  // [T, H]
    const float* gw  = (const float*)d_in[1];  // [H, E]
    const float* w1  = (const float*)d_in[2];  // [E, H, I]
    const float* w3  = (const float*)d_in[3];  // [E, H, I]
    const float* w2  = (const float*)d_in[4];  // [E, I, H]
    const float* sw1 = (const float*)d_in[5];  // [H, Is]
    const float* sw3 = (const float*)d_in[6];  // [H, Is]
    const float* sw2 = (const float*)d_in[7];  // [Is, H]
    const float* sgw = (const float*)d_in[8];  // [H, 1]
    float* out = (float*)d_out;

    const int T = in_sizes[0] / HDIM;  // 8192
    const int TK = T * TOPK;

    // resolve device-global scratch addresses (host API, not a stream op)
    float *sG, *sH, *topw, *bw, *gatev;
    int *topi, *counts, *offsets, *cursor, *btok;
    cudaGetSymbolAddress((void**)&sG, g_scratchG);
    cudaGetSymbolAddress((void**)&sH, g_scratchH);
    cudaGetSymbolAddress((void**)&topi, g_topi);
    cudaGetSymbolAddress((void**)&topw, g_topw);
    cudaGetSymbolAddress((void**)&gatev, g_gate);
    cudaGetSymbolAddress((void**)&counts, g_counts);
    cudaGetSymbolAddress((void**)&offsets, g_offsets);
    cudaGetSymbolAddress((void**)&cursor, g_cursor);
    cudaGetSymbolAddress((void**)&btok, g_btok);
    cudaGetSymbolAddress((void**)&bw, g_bw);

    // ---- routing ----
    zero_counts_k<<<1, 32>>>(counts);
    router_k<<<T, 256>>>(x, gw, sgw, topi, topw, gatev, counts);
    prefix_k<<<1, 32>>>(counts, offsets, cursor);
    scatter_k<<<(TK + 255) / 256, 256>>>(topi, topw, cursor, btok, bw, TK);

    // ---- shared expert: out = sigmoid(x@sg_w) * ((silu(x@sw1) * (x@sw3)) @ sw2)
    {
        dim3 grid1(ISDIM / BN, T / BM);
        gemm_k<M_STORE, false><<<grid1, 256>>>(
            x, sw1, sG, nullptr, nullptr, nullptr, nullptr, nullptr, nullptr,
            T, ISDIM, HDIM);
        gemm_k<M_SILUMUL, false><<<grid1, 256>>>(
            x, sw3, sH, sG, nullptr, nullptr, nullptr, nullptr, nullptr,
            T, ISDIM, HDIM);
        dim3 grid2(HDIM / BN, T / BM);
        gemm_k<M_SCALESTORE, false><<<grid2, 256>>>(
            sH, sw2, out, nullptr, gatev, nullptr, nullptr, nullptr, nullptr,
            T, HDIM, ISDIM);   // writes ALL of d_out (covers 0xAA poison)
    }

    // ---- routed experts (token-grouped, sparse) ----
    {
        dim3 grid1(IDIM / BN, T / BM, NEXP);
        gemm_k<M_STORE, true><<<grid1, 256>>>(
            x, w1, sG, nullptr, nullptr, counts, offsets, btok, bw,
            T, IDIM, HDIM);
        gemm_k<M_SILUMUL, true><<<grid1, 256>>>(
            x, w3, sH, sG, nullptr, counts, offsets, btok, bw,
            T, IDIM, HDIM);
        dim3 grid2(HDIM / BN, T / BM, NEXP);
        gemm_k<M_SCATTER, true><<<grid2, 256>>>(
            sH, w2, out, nullptr, nullptr, counts, offsets, btok, bw,
            T, HDIM, IDIM);
    }
}

// round 8
// speedup vs baseline: 1.9276x; 1.9262x over previous
#include <cuda_runtime.h>
#include <cuda_bf16.h>
#include <math.h>
#include <stdint.h>

#define HDIM 2048
#define NEXP 16
#define TOPK 4
#define IDIM 1408
#define ISDIM 5632
#define TMAX 8192
#define TKMAX (TMAX * TOPK)

typedef unsigned short u16;
typedef unsigned int u32;

// ---------------------------------------------------------------------------
// Device scratch (static device globals; no allocations anywhere)
// ---------------------------------------------------------------------------
#define WEXP ((size_t)NEXP * HDIM * IDIM)   // 46,137,344
#define WSH ((size_t)HDIM * ISDIM)          // 11,534,336
#define HELEMS ((size_t)46137344)           // == T*Is == T*K*I

__device__ u16 g_w1h[WEXP], g_w1l[WEXP];
__device__ u16 g_w3h[WEXP], g_w3l[WEXP];
__device__ u16 g_w2h[WEXP], g_w2l[WEXP];
__device__ u16 g_s1h[WSH], g_s1l[WSH];
__device__ u16 g_s3h[WSH], g_s3l[WSH];
__device__ u16 g_s2h[WSH], g_s2l[WSH];
__device__ u16 g_xh[(size_t)TMAX * HDIM], g_xl[(size_t)TMAX * HDIM];
__device__ u16 g_hh[HELEMS], g_hl[HELEMS];
__device__ float g_G[HELEMS];                   // fp32 gate-proj buffer
__device__ float g_dtmp[(size_t)TKMAX * HDIM];  // routed down rows (compact)
__device__ int g_topi[TKMAX], g_btok[TKMAX], g_posmap[TKMAX];
__device__ float g_topw[TKMAX], g_gate[TMAX];
__device__ int g_counts[NEXP], g_offsets[NEXP], g_cursor[NEXP];

// ---------------------------------------------------------------------------
// PTX helpers (all base sm_80+ features: cp.async, ldmatrix, mma.sync bf16)
// ---------------------------------------------------------------------------
__device__ __forceinline__ u32 s2u(const void* p) {
    u32 a;
    asm("{ .reg .u64 t; cvta.to.shared.u64 t, %1; cvt.u32.u64 %0, t; }"
        : "=r"(a) : "l"(p));
    return a;
}
__device__ __forceinline__ void cp16(u32 d, const void* s) {
    asm volatile("cp.async.cg.shared.global [%0], [%1], 16;"
                 :: "r"(d), "l"(s) : "memory");
}
__device__ __forceinline__ void ldsm_x4(u32 a, u32& r0, u32& r1, u32& r2, u32& r3) {
    asm volatile("ldmatrix.sync.aligned.m8n8.x4.shared.b16 {%0,%1,%2,%3}, [%4];"
                 : "=r"(r0), "=r"(r1), "=r"(r2), "=r"(r3) : "r"(a));
}
__device__ __forceinline__ void ldsm_x2(u32 a, u32& r0, u32& r1) {
    asm volatile("ldmatrix.sync.aligned.m8n8.x2.shared.b16 {%0,%1}, [%2];"
                 : "=r"(r0), "=r"(r1) : "r"(a));
}
__device__ __forceinline__ void mma16816(float* c, u32 a0, u32 a1, u32 a2, u32 a3,
                                         u32 b0, u32 b1) {
    asm volatile(
        "mma.sync.aligned.m16n8k16.row.col.f32.bf16.bf16.f32 "
        "{%0,%1,%2,%3}, {%4,%5,%6,%7}, {%8,%9}, {%0,%1,%2,%3};"
        : "+f"(c[0]), "+f"(c[1]), "+f"(c[2]), "+f"(c[3])
        : "r"(a0), "r"(a1), "r"(a2), "r"(a3), "r"(b0), "r"(b1));
}

// ---------------------------------------------------------------------------
// Router + bucketing
// ---------------------------------------------------------------------------
__global__ void router_k(const float* __restrict__ x, const float* __restrict__ gw,
                         const float* __restrict__ sgw,
                         int* __restrict__ topi, float* __restrict__ topw,
                         float* __restrict__ gatev, int* __restrict__ counts) {
    int t = blockIdx.x;
    const float* xr = x + (size_t)t * HDIM;
    float acc[17];
#pragma unroll
    for (int e = 0; e < 17; e++) acc[e] = 0.f;
    for (int h = threadIdx.x; h < HDIM; h += blockDim.x) {
        float xv = xr[h];
        const float* g = gw + h * NEXP;
#pragma unroll
        for (int e = 0; e < NEXP; e++) acc[e] += xv * g[e];
        acc[16] += xv * sgw[h];
    }
    __shared__ float red[17][8];
    int lane = threadIdx.x & 31, w = threadIdx.x >> 5;
#pragma unroll
    for (int e = 0; e < 17; e++) {
        float v = acc[e];
#pragma unroll
        for (int o = 16; o; o >>= 1) v += __shfl_down_sync(0xffffffffu, v, o);
        if (lane == 0) red[e][w] = v;
    }
    __syncthreads();
    if (threadIdx.x == 0) {
        float l[17];
#pragma unroll
        for (int e = 0; e < 17; e++) {
            float s = 0.f;
#pragma unroll
            for (int i = 0; i < 8; i++) s += red[e][i];
            l[e] = s;
        }
        float mx = l[0];
#pragma unroll
        for (int e = 1; e < NEXP; e++) mx = fmaxf(mx, l[e]);
        float p[NEXP], sum = 0.f;
#pragma unroll
        for (int e = 0; e < NEXP; e++) { p[e] = expf(l[e] - mx); sum += p[e]; }
        float inv = 1.f / sum;
        bool used[NEXP];
#pragma unroll
        for (int e = 0; e < NEXP; e++) used[e] = false;
        for (int k = 0; k < TOPK; k++) {
            int best = 0; float bv = -1.f;
#pragma unroll
            for (int e = 0; e < NEXP; e++)
                if (!used[e] && p[e] > bv) { bv = p[e]; best = e; }
            used[best] = true;
            topi[t * TOPK + k] = best;
            topw[t * TOPK + k] = bv * inv;
            atomicAdd(&counts[best], 1);
        }
        gatev[t] = 1.f / (1.f + expf(-l[16]));
    }
}

__global__ void zero_counts_k(int* __restrict__ c) {
    if (threadIdx.x < NEXP) c[threadIdx.x] = 0;
}
__global__ void prefix_k(const int* __restrict__ c, int* __restrict__ off,
                         int* __restrict__ cur) {
    if (threadIdx.x == 0) {
        int s = 0;
        for (int e = 0; e < NEXP; e++) { off[e] = s; cur[e] = s; s += c[e]; }
    }
}
__global__ void scatter_k(const int* __restrict__ topi, int* __restrict__ cur,
                          int* __restrict__ btok, int* __restrict__ posmap, int TK) {
    int i = blockIdx.x * blockDim.x + threadIdx.x;
    if (i < TK) {
        int pos = atomicAdd(&cur[topi[i]], 1);
        btok[pos] = i >> 2;
        posmap[i] = pos;
    }
}

// ---------------------------------------------------------------------------
// Prep: split x into bf16 hi/lo; transpose+split weights [K,N] -> [N,K] hi/lo
// ---------------------------------------------------------------------------
__global__ void splitx_k(const float* __restrict__ x, u16* __restrict__ xh,
                         u16* __restrict__ xl, size_t n) {
    size_t i = (size_t)blockIdx.x * blockDim.x + threadIdx.x;
    if (i < n) {
        float v = x[i];
        __nv_bfloat16 h = __float2bfloat16(v);
        float rem = v - __bfloat162float(h);
        xh[i] = __bfloat16_as_ushort(h);
        xl[i] = __bfloat16_as_ushort(__float2bfloat16(rem));
    }
}

__global__ void tsplit_k(const float* __restrict__ in, u16* __restrict__ oh,
                         u16* __restrict__ ol, int K, int N) {
    __shared__ float t[32][33];
    size_t eo = (size_t)blockIdx.z * K * N;
    int n0 = blockIdx.x * 32, k0 = blockIdx.y * 32;
    for (int i = threadIdx.y; i < 32; i += 8)
        t[i][threadIdx.x] = in[eo + (size_t)(k0 + i) * N + n0 + threadIdx.x];
    __syncthreads();
    for (int i = threadIdx.y; i < 32; i += 8) {
        float v = t[threadIdx.x][i];
        __nv_bfloat16 h = __float2bfloat16(v);
        float rem = v - __bfloat162float(h);
        size_t o = eo + (size_t)(n0 + i) * K + k0 + threadIdx.x;
        oh[o] = __bfloat16_as_ushort(h);
        ol[o] = __bfloat16_as_ushort(__float2bfloat16(rem));
    }
}

// ---------------------------------------------------------------------------
// HMMA GEMM (bf16x3 via mma.sync.m16n8k16), 128x128 tile, BK=32, 2 stages.
//   A [M,K] row-major (hi/lo), B [N,K] row-major (hi/lo) == col-major k x n.
//   MODE 0 STORE:   G[(orow)*N+n] = acc                (fp32)
//   MODE 1 SILUMUL: h = silu(G)*acc -> Hh/Hl split bf16
//   MODE 2 DOWNSH:  Fout[m*N+n] = gate[m]*acc          (dense out)
//   MODE 3 DOWNRT:  Fout[(off+m)*N+n] = acc            (compact dtmp)
// ROUTED: blockIdx.z = expert; A rows via btok gather (mode 0/1) or compact.
// ---------------------------------------------------------------------------
#define TILE_B 10240            // 128 rows * 80B (64B data + 16B pad)
#define STAGE_B (4 * TILE_B)    // Ah, Al, Bh, Bl

template <int MODE, bool ROUTED>
__global__ void __launch_bounds__(256)
hmma_k(const u16* __restrict__ Ah, const u16* __restrict__ Al,
       const u16* __restrict__ Bh, const u16* __restrict__ Bl,
       float* __restrict__ G, u16* __restrict__ Hh, u16* __restrict__ Hl,
       float* __restrict__ Fout, const float* __restrict__ gate,
       const int* __restrict__ counts, const int* __restrict__ offsets,
       const int* __restrict__ btok, int M, int N, int Kd) {
    int Ne = M, off = 0;
    if (ROUTED) {
        int e = blockIdx.z;
        Ne = counts[e];
        off = offsets[e];
        size_t wo = (size_t)e * N * Kd;
        Bh += wo; Bl += wo;
    }
    int rowblock = blockIdx.y * 128;
    if (rowblock >= Ne) return;
    int colblock = blockIdx.x * 128;

    extern __shared__ char dynsm[];
    u32 sbase = s2u(dynsm);

    int tid = threadIdx.x;
    int lane = tid & 31, wid = tid >> 5;
    int wm = wid >> 2, wn = wid & 3;   // warp tile: rows wm*64, cols wn*32

    // ---- loader: 8 x 16B cp.async per thread per chunk ----
    const char* gptr[8];
    u32 soff[8];
#pragma unroll
    for (int j = 0; j < 8; j++) {
        int i = tid + 256 * j;
        int tile = i >> 9;          // 0 Ah, 1 Al, 2 Bh, 3 Bl
        int idx = i & 511;
        int row = idx >> 2, cc = idx & 3;
        soff[j] = tile * TILE_B + row * 80 + cc * 16;
        const u16* bp;
        if (tile < 2) {
            int m = rowblock + row;
            int mc = (m < Ne) ? m : (Ne - 1);
            size_t gr;
            if (ROUTED) gr = (MODE == 3) ? (size_t)(off + mc) : (size_t)btok[off + mc];
            else gr = (size_t)mc;
            bp = (tile == 0 ? Ah : Al) + gr * Kd;
        } else {
            bp = (tile == 2 ? Bh : Bl) + (size_t)(colblock + row) * Kd;
        }
        gptr[j] = (const char*)bp + cc * 16;
    }

    const int NC = Kd >> 5;  // BK = 32

    auto load_chunk = [&](int c, int s) {
        u32 stg = sbase + s * STAGE_B;
        int kb = c * 64;  // byte offset: 32 halves
#pragma unroll
        for (int j = 0; j < 8; j++) cp16(stg + soff[j], gptr[j] + kb);
        asm volatile("cp.async.commit_group;" ::: "memory");
    };

    float acc[4][4][4];
#pragma unroll
    for (int a = 0; a < 4; a++)
#pragma unroll
        for (int b = 0; b < 4; b++)
#pragma unroll
            for (int d = 0; d < 4; d++) acc[a][b][d] = 0.f;

    // ldmatrix per-lane byte offsets (within a tile)
    u32 aoff = (u32)(((lane & 7) + ((lane >> 3) & 1) * 8) * 80 + ((lane >> 4) & 1) * 16);
    int l16 = lane & 15;
    u32 boff = (u32)((l16 & 7) * 80 + ((l16 >> 3) & 1) * 16);

    load_chunk(0, 0);
    load_chunk(1, 1);

    for (int c = 0; c < NC; c++) {
        int s = c & 1;
        if (c + 1 < NC) asm volatile("cp.async.wait_group 1;" ::: "memory");
        else            asm volatile("cp.async.wait_group 0;" ::: "memory");
        __syncthreads();

        u32 ab = sbase + s * STAGE_B;
#pragma unroll
        for (int kk = 0; kk < 2; kk++) {
            u32 ah[4][4], al[4][4], bh[4][2], bl[4][2];
#pragma unroll
            for (int mt = 0; mt < 4; mt++) {
                u32 addr = ab + (u32)((wm * 64 + mt * 16) * 80) + aoff + kk * 32;
                ldsm_x4(addr, ah[mt][0], ah[mt][1], ah[mt][2], ah[mt][3]);
                ldsm_x4(addr + TILE_B, al[mt][0], al[mt][1], al[mt][2], al[mt][3]);
            }
#pragma unroll
            for (int nt = 0; nt < 4; nt++) {
                u32 addr = ab + 2 * TILE_B + (u32)((wn * 32 + nt * 8) * 80) + boff + kk * 32;
                ldsm_x2(addr, bh[nt][0], bh[nt][1]);
                ldsm_x2(addr + TILE_B, bl[nt][0], bl[nt][1]);
            }
#pragma unroll
            for (int mt = 0; mt < 4; mt++)
#pragma unroll
                for (int nt = 0; nt < 4; nt++) {
                    mma16816(acc[mt][nt], ah[mt][0], ah[mt][1], ah[mt][2], ah[mt][3],
                             bh[nt][0], bh[nt][1]);
                    mma16816(acc[mt][nt], ah[mt][0], ah[mt][1], ah[mt][2], ah[mt][3],
                             bl[nt][0], bl[nt][1]);
                    mma16816(acc[mt][nt], al[mt][0], al[mt][1], al[mt][2], al[mt][3],
                             bh[nt][0], bh[nt][1]);
                }
        }
        __syncthreads();
        if (c + 2 < NC) load_chunk(c + 2, s);
    }

    // ---- epilogue ----
    int g = lane >> 2, q = lane & 3;
#pragma unroll
    for (int mt = 0; mt < 4; mt++) {
#pragma unroll
        for (int h2 = 0; h2 < 2; h2++) {
            int m = rowblock + wm * 64 + mt * 16 + g + 8 * h2;
            if (m >= Ne) continue;
            size_t orow = (size_t)((ROUTED ? off : 0) + m);
            float gsc = (MODE == 2) ? gate[m] : 1.f;
#pragma unroll
            for (int nt = 0; nt < 4; nt++) {
                int n = colblock + wn * 32 + nt * 8 + 2 * q;
                float v0 = acc[mt][nt][2 * h2 + 0];
                float v1 = acc[mt][nt][2 * h2 + 1];
                if (MODE == 0) {
                    *(float2*)&G[orow * N + n] = make_float2(v0, v1);
                } else if (MODE == 1) {
                    float2 gg = *(const float2*)&G[orow * N + n];
                    float h0 = (gg.x / (1.f + expf(-gg.x))) * v0;
                    float h1 = (gg.y / (1.f + expf(-gg.y))) * v1;
                    __nv_bfloat16 b0 = __float2bfloat16(h0);
                    __nv_bfloat16 b1 = __float2bfloat16(h1);
                    u16 l0 = __bfloat16_as_ushort(__float2bfloat16(h0 - __bfloat162float(b0)));
                    u16 l1 = __bfloat16_as_ushort(__float2bfloat16(h1 - __bfloat162float(b1)));
                    *(u32*)&Hh[orow * N + n] =
                        (u32)__bfloat16_as_ushort(b0) | ((u32)__bfloat16_as_ushort(b1) << 16);
                    *(u32*)&Hl[orow * N + n] = (u32)l0 | ((u32)l1 << 16);
                } else if (MODE == 2) {
                    *(float2*)&Fout[(size_t)m * N + n] = make_float2(gsc * v0, gsc * v1);
                } else {
                    *(float2*)&Fout[orow * N + n] = make_float2(v0, v1);
                }
            }
        }
    }
}

// ---------------------------------------------------------------------------
// Combine: out[t,:] += sum_k topw[t,k] * dtmp[posmap[t,k],:]
// ---------------------------------------------------------------------------
__global__ void combine_k(float* __restrict__ out, const float* __restrict__ dtmp,
                          const int* __restrict__ posmap, const float* __restrict__ topw,
                          int T) {
    int idx = blockIdx.x * blockDim.x + threadIdx.x;
    int HV = HDIM / 4;
    if (idx >= T * HV) return;
    int t = idx / HV, hv = idx % HV;
    float4 o = ((const float4*)out)[idx];
#pragma unroll
    for (int k = 0; k < TOPK; k++) {
        int p = posmap[t * TOPK + k];
        float w = topw[t * TOPK + k];
        float4 d = ((const float4*)dtmp)[(size_t)p * HV + hv];
        o.x += w * d.x; o.y += w * d.y; o.z += w * d.z; o.w += w * d.w;
    }
    ((float4*)out)[idx] = o;
}

// ---------------------------------------------------------------------------
// kernel_launch
// ---------------------------------------------------------------------------
extern "C" void kernel_launch(void* const* d_in, const int* in_sizes, int n_in,
                              void* d_out, int out_size) {
    const float* x   = (const float*)d_in[0];
    const float* gw  = (const float*)d_in[1];
    const float* w1  = (const float*)d_in[2];
    const float* w3  = (const float*)d_in[3];
    const float* w2  = (const float*)d_in[4];
    const float* sw1 = (const float*)d_in[5];
    const float* sw3 = (const float*)d_in[6];
    const float* sw2 = (const float*)d_in[7];
    const float* sgw = (const float*)d_in[8];
    float* out = (float*)d_out;

    const int T = in_sizes[0] / HDIM;   // 8192
    const int TK = T * TOPK;

    u16 *w1h, *w1l, *w3h, *w3l, *w2h, *w2l;
    u16 *s1h, *s1l, *s3h, *s3l, *s2h, *s2l, *xh, *xl, *hh, *hl;
    float *G, *dtmp, *topw, *gatev;
    int *topi, *counts, *offsets, *cursor, *btok, *posmap;
    cudaGetSymbolAddress((void**)&w1h, g_w1h); cudaGetSymbolAddress((void**)&w1l, g_w1l);
    cudaGetSymbolAddress((void**)&w3h, g_w3h); cudaGetSymbolAddress((void**)&w3l, g_w3l);
    cudaGetSymbolAddress((void**)&w2h, g_w2h); cudaGetSymbolAddress((void**)&w2l, g_w2l);
    cudaGetSymbolAddress((void**)&s1h, g_s1h); cudaGetSymbolAddress((void**)&s1l, g_s1l);
    cudaGetSymbolAddress((void**)&s3h, g_s3h); cudaGetSymbolAddress((void**)&s3l, g_s3l);
    cudaGetSymbolAddress((void**)&s2h, g_s2h); cudaGetSymbolAddress((void**)&s2l, g_s2l);
    cudaGetSymbolAddress((void**)&xh, g_xh);   cudaGetSymbolAddress((void**)&xl, g_xl);
    cudaGetSymbolAddress((void**)&hh, g_hh);   cudaGetSymbolAddress((void**)&hl, g_hl);
    cudaGetSymbolAddress((void**)&G, g_G);
    cudaGetSymbolAddress((void**)&dtmp, g_dtmp);
    cudaGetSymbolAddress((void**)&topi, g_topi);
    cudaGetSymbolAddress((void**)&topw, g_topw);
    cudaGetSymbolAddress((void**)&gatev, g_gate);
    cudaGetSymbolAddress((void**)&counts, g_counts);
    cudaGetSymbolAddress((void**)&offsets, g_offsets);
    cudaGetSymbolAddress((void**)&cursor, g_cursor);
    cudaGetSymbolAddress((void**)&btok, g_btok);
    cudaGetSymbolAddress((void**)&posmap, g_posmap);

    const int SMEM = 2 * STAGE_B;  // 81,920
    cudaFuncSetAttribute(hmma_k<0, false>, cudaFuncAttributeMaxDynamicSharedMemorySize, SMEM);
    cudaFuncSetAttribute(hmma_k<1, false>, cudaFuncAttributeMaxDynamicSharedMemorySize, SMEM);
    cudaFuncSetAttribute(hmma_k<2, false>, cudaFuncAttributeMaxDynamicSharedMemorySize, SMEM);
    cudaFuncSetAttribute(hmma_k<0, true>,  cudaFuncAttributeMaxDynamicSharedMemorySize, SMEM);
    cudaFuncSetAttribute(hmma_k<1, true>,  cudaFuncAttributeMaxDynamicSharedMemorySize, SMEM);
    cudaFuncSetAttribute(hmma_k<3, true>,  cudaFuncAttributeMaxDynamicSharedMemorySize, SMEM);

    // ---- routing ----
    zero_counts_k<<<1, 32>>>(counts);
    router_k<<<T, 256>>>(x, gw, sgw, topi, topw, gatev, counts);
    prefix_k<<<1, 32>>>(counts, offsets, cursor);
    scatter_k<<<(TK + 255) / 256, 256>>>(topi, cursor, btok, posmap, TK);

    // ---- prep: splits + transposes ----
    {
        size_t n = (size_t)T * HDIM;
        splitx_k<<<(int)((n + 255) / 256), 256>>>(x, xh, xl, n);
        dim3 b(32, 8);
        tsplit_k<<<dim3(IDIM / 32, HDIM / 32, NEXP), b>>>(w1, w1h, w1l, HDIM, IDIM);
        tsplit_k<<<dim3(IDIM / 32, HDIM / 32, NEXP), b>>>(w3, w3h, w3l, HDIM, IDIM);
        tsplit_k<<<dim3(HDIM / 32, IDIM / 32, NEXP), b>>>(w2, w2h, w2l, IDIM, HDIM);
        tsplit_k<<<dim3(ISDIM / 32, HDIM / 32, 1), b>>>(sw1, s1h, s1l, HDIM, ISDIM);
        tsplit_k<<<dim3(ISDIM / 32, HDIM / 32, 1), b>>>(sw3, s3h, s3l, HDIM, ISDIM);
        tsplit_k<<<dim3(HDIM / 32, ISDIM / 32, 1), b>>>(sw2, s2h, s2l, ISDIM, HDIM);
    }

    // ---- shared expert ----
    hmma_k<0, false><<<dim3(ISDIM / 128, T / 128), 256, SMEM>>>(
        xh, xl, s1h, s1l, G, nullptr, nullptr, nullptr, nullptr,
        nullptr, nullptr, nullptr, T, ISDIM, HDIM);
    hmma_k<1, false><<<dim3(ISDIM / 128, T / 128), 256, SMEM>>>(
        xh, xl, s3h, s3l, G, hh, hl, nullptr, nullptr,
        nullptr, nullptr, nullptr, T, ISDIM, HDIM);
    hmma_k<2, false><<<dim3(HDIM / 128, T / 128), 256, SMEM>>>(
        hh, hl, s2h, s2l, nullptr, nullptr, nullptr, out, gatev,
        nullptr, nullptr, nullptr, T, HDIM, ISDIM);

    // ---- routed experts ----
    hmma_k<0, true><<<dim3(IDIM / 128, TK / 128, NEXP), 256, SMEM>>>(
        xh, xl, w1h, w1l, G, nullptr, nullptr, nullptr, nullptr,
        counts, offsets, btok, TK, IDIM, HDIM);
    hmma_k<1, true><<<dim3(IDIM / 128, TK / 128, NEXP), 256, SMEM>>>(
        xh, xl, w3h, w3l, G, hh, hl, nullptr, nullptr,
        counts, offsets, btok, TK, IDIM, HDIM);
    hmma_k<3, true><<<dim3(HDIM / 128, TK / 128, NEXP), 256, SMEM>>>(
        hh, hl, w2h, w2l, nullptr, nullptr, nullptr, dtmp, nullptr,
        counts, offsets, btok, TK, HDIM, IDIM);

    // ---- combine ----
    combine_k<<<(T * (HDIM / 4) + 255) / 256, 256>>>(out, dtmp, posmap, topw, T);
}